// round 13
// baseline (speedup 1.0000x reference)
#include <cuda_runtime.h>
#include <cuda_bf16.h>
#include <math_constants.h>
#include <cstdint>

// VQ-VAE vector quantizer via warp-level bf16 mma.sync + exact fp32 repair.
// Frozen reference pipeline (bitwise): d_k = fl(fl(A-2M_k)+B_k), A = x^2
// float2-leaf tree, M_k = ascending-d fp32 FMA chain, B_k = ascending chain,
// argmin tie -> lowest index.
// Approx phase: M~ = Ah.Bh + Ah.Bl + Al.Bh (bf16 splits, f32 acc). Approx
// score drops A (argmin-invariant): s_k = (B_k + 0.125) - 2M~_k > 0, packed
// order-isomorphically into u32 = (bits(s) & ~0x3FF) | k. Branch-free top-3
// via 5x IMNMX insert. |s - exact_shifted| <= delta ~ 4e-5; EPS=3e-4 >= 2d.
// If q3 > q1+EPS: exact argmin provably in {i1,i2} -> frozen-chain repair;
// else rare full exact scan.

#define ENC_OFF   4194304
#define LOSS_OFF  4259840
#define NLL_OFF   4259841
#define TOTAL_OUT 4259842
#define NTILES    512
#define EPS       3.0e-4f
#define BROW      72        // bf16 elems per image row (144 B, LDSM conflict-free)

// smem offsets (bytes)
#define SM_XS    0          // fp32 X tile [64][128]        32768
#define SM_AH    32768      // A-hi bf16 [128][72]          18432
#define SM_AL    51200      // A-lo bf16 [128][72]          18432
#define SM_BB    69632      // B bufs: (Bh|Bl) x2           36864
#define SM_EBS   106496     // fp32 ||e||^2 [1024]           4096
#define SM_AS    110592     // fp32 A [128]                   512
#define SM_IDX   111104     // winners [128]                  512
#define SM_WSUM  111616
#define SM_CNT   111680
#define SM_LIST  111696     // fallback list [128]            512
#define SM_TOTAL 112256
// candidate arrays overlay SM_BB after the MMA phase (u32 packed):
#define CB1 (SM_BB)
#define CB2 (SM_BB + 512)
#define CB3 (SM_BB + 1024)

typedef unsigned long long ull;
typedef unsigned int u32;

__device__ double g_loss_acc;                 // self-reset
__device__ int    g_fin;                      // self-reset
__device__ __align__(16) float g_eB[1024];    // exact ||e||^2 chains
__device__ __align__(16) __nv_bfloat16 g_Bh[1024 * BROW];  // hi image (padded rows)
__device__ __align__(16) __nv_bfloat16 g_Bl[1024 * BROW];  // lo image

__device__ __forceinline__ void cp16(u32 dst, const void* src) {
    asm volatile("cp.async.cg.shared.global [%0], [%1], 16;"
                 :: "r"(dst), "l"(src) : "memory");
}
#define CP_COMMIT() asm volatile("cp.async.commit_group;" ::: "memory")
#define CP_WAIT0()  asm volatile("cp.async.wait_group 0;" ::: "memory")
#define CP_WAIT1()  asm volatile("cp.async.wait_group 1;" ::: "memory")

#define LDSM_X4(r, a)                                                        \
    asm volatile("ldmatrix.sync.aligned.m8n8.x4.shared.b16 {%0,%1,%2,%3}, [%4];" \
        : "=r"((r)[0]), "=r"((r)[1]), "=r"((r)[2]), "=r"((r)[3]) : "r"(a))
#define MMA_BF16(c, a, b0, b1)                                               \
    asm volatile("mma.sync.aligned.m16n8k16.row.col.f32.bf16.bf16.f32 "      \
        "{%0,%1,%2,%3}, {%4,%5,%6,%7}, {%8,%9}, {%0,%1,%2,%3};"              \
        : "+f"((c)[0]), "+f"((c)[1]), "+f"((c)[2]), "+f"((c)[3])             \
        : "r"((a)[0]), "r"((a)[1]), "r"((a)[2]), "r"((a)[3]), "r"(b0), "r"(b1))

// branch-free sorted top-3 insert: 5 IMNMX. Invariant a1<=a2<=a3.
__device__ __forceinline__ void ins3(u32& a1, u32& a2, u32& a3, u32 v) {
    u32 hi  = a1 > v ? a1 : v;  a1 = a1 < v ? a1 : v;
    u32 hi2 = a2 > hi ? a2 : hi; a2 = a2 < hi ? a2 : hi;
    a3 = a3 < hi2 ? a3 : hi2;
}

// Kernel 0: bf16 hi/lo codebook images (padded rows) + exact ||e||^2 chains.
__global__ void __launch_bounds__(256) vq_prep(const float* __restrict__ emb) {
    int t = blockIdx.x * blockDim.x + threadIdx.x;   // 65536
    int k = t >> 6, d = t & 63;
    float e = emb[t];
    __nv_bfloat16 hh = __float2bfloat16(e);
    __nv_bfloat16 ll = __float2bfloat16(__fadd_rn(e, -__bfloat162float(hh)));
    g_Bh[k * BROW + d] = hh;
    g_Bl[k * BROW + d] = ll;
    if (t < 1024) {
        const float* row = emb + (size_t)t * 64;
        float b = 0.0f;
        #pragma unroll
        for (int i = 0; i < 64; i++) b = __fmaf_rn(row[i], row[i], b);
        g_eB[t] = b;
    }
}

__global__ void __launch_bounds__(256, 2)
vq_main(const float* __restrict__ x, const float* __restrict__ emb,
        float* __restrict__ out, int out_size) {
    extern __shared__ __align__(1024) unsigned char sm[];
    float* Xs   = (float*)(sm + SM_XS);
    float* eBs  = (float*)(sm + SM_EBS);
    float* As   = (float*)(sm + SM_AS);
    int*   idxs = (int*)(sm + SM_IDX);
    float* wsum = (float*)(sm + SM_WSUM);
    int*   scnt = (int*)(sm + SM_CNT);
    int*   slist = (int*)(sm + SM_LIST);

    const u32 base = (u32)__cvta_generic_to_shared(sm);
    const int tid = threadIdx.x;
    const int wid = tid >> 5, lane = tid & 31;
    const int b  = blockIdx.x >> 3;
    const int p0 = (blockIdx.x & 7) * 128;
    const int m0 = wid * 16;

    if (tid == 0) *scnt = 0;

    // ---- prologue: group0 = X + eB, group1 = B chunk 0 ----
    {
        const float* xb = x + (size_t)b * 65536 + p0;
        #pragma unroll
        for (int i = 0; i < 8; i++) {
            int c = tid + i * 256;           // 2048 16B-chunks
            int d = c >> 5, po = c & 31;
            cp16(base + SM_XS + d * 512 + po * 16, xb + d * 1024 + po * 4);
        }
        cp16(base + SM_EBS + tid * 16, (const char*)g_eB + tid * 16);
        CP_COMMIT();
        #pragma unroll
        for (int i = 0; i < 5; i++) {        // 1152 chunks (Bh 576 + Bl 576)
            int c = tid + i * 256;
            if (c < 1152) {
                int sp = c >= 576;
                int cc = c - sp * 576;
                const char* src = (const char*)(sp ? g_Bl : g_Bh) + cc * 16;
                cp16(base + SM_BB + sp * 9216 + cc * 16, src);
            }
        }
        CP_COMMIT();
        CP_WAIT1();     // X + eB landed (B0 may still fly)
    }
    __syncthreads();

    // ---- build Ah/Al bf16 images (row = position, 144B stride) ----
    if (tid < 128) {
        #pragma unroll
        for (int d2 = 0; d2 < 32; d2++) {
            float v0 = Xs[(2 * d2) * 128 + tid];
            float v1 = Xs[(2 * d2 + 1) * 128 + tid];
            __nv_bfloat16 h0 = __float2bfloat16(v0), h1 = __float2bfloat16(v1);
            __nv_bfloat16 l0 = __float2bfloat16(__fadd_rn(v0, -__bfloat162float(h0)));
            __nv_bfloat16 l1 = __float2bfloat16(__fadd_rn(v1, -__bfloat162float(h1)));
            u32 hw = (u32)*(unsigned short*)&h0 | ((u32)*(unsigned short*)&h1 << 16);
            u32 lw = (u32)*(unsigned short*)&l0 | ((u32)*(unsigned short*)&l1 << 16);
            *(u32*)(sm + SM_AH + tid * 144 + d2 * 4) = hw;
            *(u32*)(sm + SM_AL + tid * 144 + d2 * 4) = lw;
        }
        // A_p exact: float2 leaves + binary tree (frozen order)
        float l[32];
        #pragma unroll
        for (int t = 0; t < 32; t++) {
            float a = Xs[(2 * t) * 128 + tid];
            float c = Xs[(2 * t + 1) * 128 + tid];
            l[t] = __fmaf_rn(c, c, __fmul_rn(a, a));
        }
        #pragma unroll
        for (int off = 16; off >= 1; off >>= 1)
            #pragma unroll
            for (int t = 0; t < 16; t++)
                if (t < off) l[t] = __fadd_rn(l[t], l[t + off]);
        As[tid] = l[0];
    }
    __syncthreads();

    // per-lane fragment addresses
    const int g = lane >> 2, tq = lane & 3;
    const int lr = (lane & 7) + ((lane >> 3) & 1) * 8;
    const u32 a_base  = base + SM_AH + (u32)((m0 + lr) * 144 + ((lane >> 4) & 1) * 16);
    const u32 al_base = a_base + (SM_AL - SM_AH);
    // B x4 address: lanes0-7 rows n0-7 k0-7; 8-15 +16B (k8-15); 16-31 rows n8-15
    const u32 b4_off = (u32)((lane & 7) * 144 + ((lane >> 3) & 1) * 16
                             + ((lane >> 4) & 1) * 1152);

    // per-lane packed top-3 state for rows m0+g and m0+8+g
    u32 Q10 = 0xFFFFFFFFu, Q20 = 0xFFFFFFFFu, Q30 = 0xFFFFFFFFu;
    u32 Q11 = 0xFFFFFFFFu, Q21 = 0xFFFFFFFFu, Q31 = 0xFFFFFFFFu;

    // ---- 16 chunks of 64 codes ----
    #pragma unroll 1
    for (int n = 0; n < 16; n++) {
        CP_WAIT0();
        __syncthreads();                 // B(n) visible; buf (n+1)&1 free

        if (n < 15) {                    // stage next chunk during compute
            const char* sbh = (const char*)g_Bh + (n + 1) * 9216;
            const char* sbl = (const char*)g_Bl + (n + 1) * 9216;
            u32 dst = base + SM_BB + (u32)(((n + 1) & 1) * 18432);
            #pragma unroll
            for (int i = 0; i < 5; i++) {
                int c = tid + i * 256;
                if (c < 1152) {
                    int sp = c >= 576;
                    int cc = c - sp * 576;
                    cp16(dst + sp * 9216 + cc * 16,
                         (sp ? sbl : sbh) + cc * 16);
                }
            }
            CP_COMMIT();
        }

        const u32 bb = base + SM_BB + (u32)((n & 1) * 18432);
        float c[8][4];
        #pragma unroll
        for (int nt = 0; nt < 8; nt++)
            #pragma unroll
            for (int q = 0; q < 4; q++) c[nt][q] = 0.0f;

        #pragma unroll
        for (int ks = 0; ks < 4; ks++) {
            u32 ah[4], al4[4];
            LDSM_X4(ah, a_base + ks * 32);
            LDSM_X4(al4, al_base + ks * 32);
            #pragma unroll
            for (int p = 0; p < 4; p++) {      // nt pair {2p, 2p+1}
                u32 bh[4], bl4[4];
                u32 ba = bb + (u32)(p * 2304 + ks * 32) + b4_off;
                LDSM_X4(bh, ba);
                LDSM_X4(bl4, ba + 9216);
                MMA_BF16(c[2 * p],     ah,  bh[0],  bh[1]);
                MMA_BF16(c[2 * p],     ah,  bl4[0], bl4[1]);
                MMA_BF16(c[2 * p],     al4, bh[0],  bh[1]);
                MMA_BF16(c[2 * p + 1], ah,  bh[2],  bh[3]);
                MMA_BF16(c[2 * p + 1], ah,  bl4[2], bl4[3]);
                MMA_BF16(c[2 * p + 1], al4, bh[2],  bh[3]);
            }
        }

        // fold: s = fl(eB+0.125) - 2M~ > 0, pack (bits & ~0x3FF) | col,
        // branch-free top-3. Ascending cols; u32 min => lowest idx on tie.
        const int n0q = n * 64;
        #pragma unroll
        for (int nt = 0; nt < 8; nt++) {
            int col = n0q + nt * 8 + 2 * tq;
            float2 eb2 = *(const float2*)&eBs[col];
            float ex = __fadd_rn(eb2.x, 0.125f);
            float ey = __fadd_rn(eb2.y, 0.125f);
            u32 s0 = (__float_as_uint(__fmaf_rn(-2.0f, c[nt][0], ex)) & 0xFFFFFC00u) | (u32)col;
            u32 s1 = (__float_as_uint(__fmaf_rn(-2.0f, c[nt][1], ey)) & 0xFFFFFC00u) | (u32)(col + 1);
            u32 s2 = (__float_as_uint(__fmaf_rn(-2.0f, c[nt][2], ex)) & 0xFFFFFC00u) | (u32)col;
            u32 s3 = (__float_as_uint(__fmaf_rn(-2.0f, c[nt][3], ey)) & 0xFFFFFC00u) | (u32)(col + 1);
            ins3(Q10, Q20, Q30, s0);
            ins3(Q10, Q20, Q30, s1);
            ins3(Q11, Q21, Q31, s2);
            ins3(Q11, Q21, Q31, s3);
        }
    }
    __syncthreads();    // all warps done reading B bufs before overlay

    // ---- cross-lane merge within column quads (xor 1, xor 2) ----
    #pragma unroll
    for (int s = 1; s <= 2; s <<= 1) {
        u32 m1 = __shfl_xor_sync(0xffffffffu, Q10, s);
        u32 m2 = __shfl_xor_sync(0xffffffffu, Q20, s);
        u32 m3 = __shfl_xor_sync(0xffffffffu, Q30, s);
        ins3(Q10, Q20, Q30, m1);
        ins3(Q10, Q20, Q30, m2);
        ins3(Q10, Q20, Q30, m3);
        m1 = __shfl_xor_sync(0xffffffffu, Q11, s);
        m2 = __shfl_xor_sync(0xffffffffu, Q21, s);
        m3 = __shfl_xor_sync(0xffffffffu, Q31, s);
        ins3(Q11, Q21, Q31, m1);
        ins3(Q11, Q21, Q31, m2);
        ins3(Q11, Q21, Q31, m3);
    }
    if (tq == 0) {
        int p = m0 + g;
        *(u32*)(sm + CB1 + p * 4) = Q10;
        *(u32*)(sm + CB2 + p * 4) = Q20;
        *(u32*)(sm + CB3 + p * 4) = Q30;
        p = m0 + 8 + g;
        *(u32*)(sm + CB1 + p * 4) = Q11;
        *(u32*)(sm + CB2 + p * 4) = Q21;
        *(u32*)(sm + CB3 + p * 4) = Q31;
    }
    __syncthreads();

    // ---- resolve winners (exact, frozen chains) ----
    if (tid < 128) {
        u32 q1 = *(u32*)(sm + CB1 + tid * 4);
        u32 q2 = *(u32*)(sm + CB2 + tid * 4);
        u32 q3 = *(u32*)(sm + CB3 + tid * 4);
        int i1 = (int)(q1 & 1023u), i2 = (int)(q2 & 1023u);
        float v1 = __uint_as_float(q1 & 0xFFFFFC00u);
        float v2 = __uint_as_float(q2 & 0xFFFFFC00u);
        float v3 = __uint_as_float(q3 & 0xFFFFFC00u);
        float thr = __fadd_rn(v1, EPS);
        if (v3 > thr) {
            int w = i1;
            if (v2 <= thr) {
                float Ap = As[tid];
                const float* e1 = emb + (size_t)i1 * 64;
                const float* e2 = emb + (size_t)i2 * 64;
                float M1 = 0.0f, M2 = 0.0f;
                #pragma unroll 4
                for (int gg = 0; gg < 16; gg++) {
                    float4 a4 = *(const float4*)(e1 + gg * 4);
                    float4 c4 = *(const float4*)(e2 + gg * 4);
                    float xv0 = Xs[(gg * 4 + 0) * 128 + tid];
                    float xv1 = Xs[(gg * 4 + 1) * 128 + tid];
                    float xv2 = Xs[(gg * 4 + 2) * 128 + tid];
                    float xv3 = Xs[(gg * 4 + 3) * 128 + tid];
                    M1 = __fmaf_rn(xv0, a4.x, M1); M2 = __fmaf_rn(xv0, c4.x, M2);
                    M1 = __fmaf_rn(xv1, a4.y, M1); M2 = __fmaf_rn(xv1, c4.y, M2);
                    M1 = __fmaf_rn(xv2, a4.z, M1); M2 = __fmaf_rn(xv2, c4.z, M2);
                    M1 = __fmaf_rn(xv3, a4.w, M1); M2 = __fmaf_rn(xv3, c4.w, M2);
                }
                float d1 = __fadd_rn(__fmaf_rn(-2.0f, M1, Ap), eBs[i1]);
                float d2 = __fadd_rn(__fmaf_rn(-2.0f, M2, Ap), eBs[i2]);
                if (d2 < d1 || (d2 == d1 && i2 < i1)) w = i2;
            }
            idxs[tid] = w;
        } else {
            int o = atomicAdd(scnt, 1);
            slist[o] = tid;
        }
    }
    __syncthreads();

    // rare full exact scan, warp-cooperative
    int cnt = *scnt;
    for (int t = wid; t < cnt; t += 8) {
        int pos = slist[t];
        float Ap2 = As[pos];
        float bd = CUDART_INF_F;
        int bi = 0;
        for (int k = lane; k < 1024; k += 32) {
            const float* er = emb + (size_t)k * 64;
            float M = 0.0f;
            #pragma unroll 4
            for (int gg = 0; gg < 16; gg++) {
                float4 e4 = *(const float4*)(er + gg * 4);
                M = __fmaf_rn(Xs[(gg * 4 + 0) * 128 + pos], e4.x, M);
                M = __fmaf_rn(Xs[(gg * 4 + 1) * 128 + pos], e4.y, M);
                M = __fmaf_rn(Xs[(gg * 4 + 2) * 128 + pos], e4.z, M);
                M = __fmaf_rn(Xs[(gg * 4 + 3) * 128 + pos], e4.w, M);
            }
            float dk = __fadd_rn(__fmaf_rn(-2.0f, M, Ap2), eBs[k]);
            if (dk < bd) { bd = dk; bi = k; }
        }
        #pragma unroll
        for (int off = 16; off > 0; off >>= 1) {
            float od = __shfl_down_sync(0xffffffffu, bd, off);
            int   oi = __shfl_down_sync(0xffffffffu, bi, off);
            if (od < bd || (od == bd && oi < bi)) { bd = od; bi = oi; }
        }
        if (lane == 0) idxs[pos] = bi;
    }
    __syncthreads();

    if (tid < 128 && out_size >= TOTAL_OUT)
        out[ENC_OFF + b * 1024 + p0 + tid] = (float)idxs[tid];

    // ---- straight-through output + loss partial ----
    float lsum = 0.0f;
    #pragma unroll
    for (int j = 0; j < 32; j++) {
        int i  = tid + j * 256;
        int pp = i & 127;
        int d  = i >> 7;
        float q  = emb[(size_t)idxs[pp] * 64 + d];
        float xv = Xs[d * 128 + pp];
        float df = __fadd_rn(q, -xv);
        lsum += df * df;
        out[((size_t)b * 64 + d) * 1024 + p0 + pp] = __fadd_rn(xv, df);
    }
    #pragma unroll
    for (int off = 16; off > 0; off >>= 1)
        lsum += __shfl_down_sync(0xffffffffu, lsum, off);
    if (lane == 0) wsum[wid] = lsum;
    __syncthreads();
    if (tid == 0) {
        float t = 0.0f;
        #pragma unroll
        for (int w = 0; w < 8; w++) t += wsum[w];
        atomicAdd(&g_loss_acc, (double)t);
        __threadfence();
        int old = atomicAdd(&g_fin, 1);
        if (old == NTILES - 1) {
            if (out_size >= TOTAL_OUT) {
                float m = (float)(g_loss_acc * (1.0 / 4194304.0));
                out[LOSS_OFF] = __fadd_rn(m, __fmul_rn(0.25f, m));
                out[NLL_OFF]  = 1.0f;
            }
            g_loss_acc = 0.0;       // self-reset for next replay
            g_fin = 0;
        }
    }
}

extern "C" void kernel_launch(void* const* d_in, const int* in_sizes, int n_in,
                              void* d_out, int out_size) {
    const float* x   = (const float*)d_in[0];
    const float* emb = (const float*)d_in[1];
    if (n_in >= 2 && in_sizes[0] == 1024 * 64) {
        const float* t = x; x = emb; emb = t;
    }
    float* out = (float*)d_out;

    cudaFuncSetAttribute(vq_main, cudaFuncAttributeMaxDynamicSharedMemorySize,
                         SM_TOTAL);

    vq_prep<<<256, 256>>>(emb);
    vq_main<<<NTILES, 256, SM_TOTAL>>>(x, emb, out, out_size);
}

// round 14
// speedup vs baseline: 1.2640x; 1.2640x over previous
#include <cuda_runtime.h>
#include <cuda_bf16.h>
#include <math_constants.h>
#include <cstdint>

// VQ-VAE quantizer: bf16-split mma.sync approx pass -> per-chunk minima ->
// chunk certificate -> grouped EXACT frozen-chain scan for winners.
// Frozen reference pipeline (bitwise): d_k = fl(fl(A-2M_k)+B_k), A = x^2
// float2-leaf tree, M_k = ascending-d fp32 FMA chain, B_k = ascending chain,
// argmin tie -> lowest index.
// Approx: M~ = Ah.Bh + Ah.Bl + Al.Bh (bf16 splits, f32 acc); s_k = fma(-2,
// M~, eB_k) (A dropped: per-position constant). Per 32-code chunk keep only
// min_k s_k -> MC[chunk][pos]. |s_k - (d_k - A)| <= delta ~ 3e-5.
// Certificate: S = {c : MC[c] <= gmin + EPS}, EPS = 3e-4 >= 2*delta.
// For k outside S: s_k > gmin+EPS => d_k - A > gmin+EPS-delta >= gmin+delta
// >= (d - A) of approx argmin => exact argmin (incl. exact ties) is in S.
// Exact scan of S's chunks with the frozen chain, ascending k, strict < =>
// bitwise-correct winner. Positions grouped per chunk; warp scans one chunk
// with broadcast emb-row loads (coalesced); u64 atomicMin combine.

#define ENC_OFF   4194304
#define LOSS_OFF  4259840
#define NLL_OFF   4259841
#define TOTAL_OUT 4259842
#define NTILES    512
#define EPS       3.0e-4f
#define BROW      72        // bf16 elems per codebook image row (144 B)
#define NCH       32        // chunks of 32 codes

// smem offsets (bytes)
#define SM_XS    0          // fp32 X tile [64][128]        32768
#define SM_AH    32768      // A-hi bf16 [128][72]          18432
#define SM_AL    51200      // A-lo bf16 [128][72]          18432
#define SM_BB    69632      // B bufs x2 (hi 4608 + lo 4608) 18432
#define SM_MC    88064      // chunk minima [32][128] f32   16384
#define SM_EBS   104448     // fp32 ||e||^2 [1024]           4096
#define SM_AS    108544     // fp32 A [128]                   512
#define SM_IDX   109056     // winners [128]                  512
#define SM_PB    109568     // u64 pbest [128]               1024
#define SM_CNTC  110592     // int cnt per chunk [32]         128
#define SM_PL    110720     // u8 plist [32][32]             1024
#define SM_WSUM  111744     // f32 [8]                         32
#define SM_TOTAL 111872

typedef unsigned long long ull;
typedef unsigned int u32;

__device__ double g_loss_acc;                 // self-reset
__device__ int    g_fin;                      // self-reset
__device__ __align__(16) float g_eB[1024];    // exact ||e||^2 chains
__device__ __align__(16) __nv_bfloat16 g_Bh[1024 * BROW];  // hi image
__device__ __align__(16) __nv_bfloat16 g_Bl[1024 * BROW];  // lo image

__device__ __forceinline__ void cp16(u32 dst, const void* src) {
    asm volatile("cp.async.cg.shared.global [%0], [%1], 16;"
                 :: "r"(dst), "l"(src) : "memory");
}
#define CP_COMMIT() asm volatile("cp.async.commit_group;" ::: "memory")
#define CP_WAIT0()  asm volatile("cp.async.wait_group 0;" ::: "memory")
#define CP_WAIT1()  asm volatile("cp.async.wait_group 1;" ::: "memory")

#define LDSM_X4(r, a)                                                        \
    asm volatile("ldmatrix.sync.aligned.m8n8.x4.shared.b16 {%0,%1,%2,%3}, [%4];" \
        : "=r"((r)[0]), "=r"((r)[1]), "=r"((r)[2]), "=r"((r)[3]) : "r"(a))
#define MMA_BF16(c, a, b0, b1)                                               \
    asm volatile("mma.sync.aligned.m16n8k16.row.col.f32.bf16.bf16.f32 "      \
        "{%0,%1,%2,%3}, {%4,%5,%6,%7}, {%8,%9}, {%0,%1,%2,%3};"              \
        : "+f"((c)[0]), "+f"((c)[1]), "+f"((c)[2]), "+f"((c)[3])             \
        : "r"((a)[0]), "r"((a)[1]), "r"((a)[2]), "r"((a)[3]), "r"(b0), "r"(b1))

// Kernel 0: bf16 hi/lo codebook images (padded rows) + exact ||e||^2 chains.
__global__ void __launch_bounds__(256) vq_prep(const float* __restrict__ emb) {
    int t = blockIdx.x * blockDim.x + threadIdx.x;   // 65536
    int k = t >> 6, d = t & 63;
    float e = emb[t];
    __nv_bfloat16 hh = __float2bfloat16(e);
    __nv_bfloat16 ll = __float2bfloat16(__fadd_rn(e, -__bfloat162float(hh)));
    g_Bh[k * BROW + d] = hh;
    g_Bl[k * BROW + d] = ll;
    if (t < 1024) {
        const float* row = emb + (size_t)t * 64;
        float b = 0.0f;
        #pragma unroll
        for (int i = 0; i < 64; i++) b = __fmaf_rn(row[i], row[i], b);
        g_eB[t] = b;
    }
}

// stage one 32-code chunk (hi+lo, 9216 B) into buffer `buf`
__device__ __forceinline__ void stage_chunk(u32 base, int c, int buf, int tid) {
    u32 dst = base + SM_BB + (u32)(buf * 9216);
    const char* sh = (const char*)g_Bh + c * 4608;
    const char* sl = (const char*)g_Bl + c * 4608;
    // 576 16B-chunks: hi 0..287, lo 288..575
    int i0 = tid;               // < 288 ? hi : lo
    {
        int sp = i0 >= 288; int off = (i0 - sp * 288) * 16;
        cp16(dst + sp * 4608 + off, (sp ? sl : sh) + off);
    }
    int i1 = tid + 256;
    {
        int sp = i1 >= 288; int off = (i1 - sp * 288) * 16;
        cp16(dst + sp * 4608 + off, (sp ? sl : sh) + off);
    }
    if (tid < 64) {
        int i2 = tid + 512;     // lo region
        int off = (i2 - 288) * 16;
        cp16(dst + 4608 + off, sl + off);
    }
}

__global__ void __launch_bounds__(256, 2)
vq_main(const float* __restrict__ x, const float* __restrict__ emb,
        float* __restrict__ out, int out_size) {
    extern __shared__ __align__(1024) unsigned char sm[];
    float* Xs    = (float*)(sm + SM_XS);
    float* MC    = (float*)(sm + SM_MC);
    float* eBs   = (float*)(sm + SM_EBS);
    float* As    = (float*)(sm + SM_AS);
    int*   idxs  = (int*)(sm + SM_IDX);
    ull*   pbest = (ull*)(sm + SM_PB);
    int*   cntc  = (int*)(sm + SM_CNTC);
    unsigned char* plist = (unsigned char*)(sm + SM_PL);
    float* wsum  = (float*)(sm + SM_WSUM);

    const u32 base = (u32)__cvta_generic_to_shared(sm);
    const int tid = threadIdx.x;
    const int wid = tid >> 5, lane = tid & 31;
    const int b  = blockIdx.x >> 3;
    const int p0 = (blockIdx.x & 7) * 128;
    const int m0 = wid * 16;

    // ---- prologue: group0 = X + eB, group1 = B chunk 0; init aux ----
    {
        const float* xb = x + (size_t)b * 65536 + p0;
        #pragma unroll
        for (int i = 0; i < 8; i++) {
            int c = tid + i * 256;           // 2048 16B-chunks
            int d = c >> 5, po = c & 31;
            cp16(base + SM_XS + d * 512 + po * 16, xb + d * 1024 + po * 4);
        }
        cp16(base + SM_EBS + tid * 16, (const char*)g_eB + tid * 16);
        CP_COMMIT();
        stage_chunk(base, 0, 0, tid);
        CP_COMMIT();
        if (tid < 128) pbest[tid] = ~0ull;
        if (tid < NCH) cntc[tid] = 0;
        CP_WAIT1();     // X + eB landed
    }
    __syncthreads();

    // ---- build Ah/Al bf16 images + exact A (frozen tree) ----
    if (tid < 128) {
        #pragma unroll
        for (int d2 = 0; d2 < 32; d2++) {
            float v0 = Xs[(2 * d2) * 128 + tid];
            float v1 = Xs[(2 * d2 + 1) * 128 + tid];
            __nv_bfloat16 h0 = __float2bfloat16(v0), h1 = __float2bfloat16(v1);
            __nv_bfloat16 l0 = __float2bfloat16(__fadd_rn(v0, -__bfloat162float(h0)));
            __nv_bfloat16 l1 = __float2bfloat16(__fadd_rn(v1, -__bfloat162float(h1)));
            u32 hw = (u32)*(unsigned short*)&h0 | ((u32)*(unsigned short*)&h1 << 16);
            u32 lw = (u32)*(unsigned short*)&l0 | ((u32)*(unsigned short*)&l1 << 16);
            *(u32*)(sm + SM_AH + tid * 144 + d2 * 4) = hw;
            *(u32*)(sm + SM_AL + tid * 144 + d2 * 4) = lw;
        }
        float l[32];
        #pragma unroll
        for (int t = 0; t < 32; t++) {
            float a = Xs[(2 * t) * 128 + tid];
            float c = Xs[(2 * t + 1) * 128 + tid];
            l[t] = __fmaf_rn(c, c, __fmul_rn(a, a));
        }
        #pragma unroll
        for (int off = 16; off >= 1; off >>= 1)
            #pragma unroll
            for (int t = 0; t < 16; t++)
                if (t < off) l[t] = __fadd_rn(l[t], l[t + off]);
        As[tid] = l[0];
    }
    __syncthreads();

    // per-lane fragment addressing (validated in R12/R13: rel_err 0)
    const int g = lane >> 2, tq = lane & 3;
    const int lr = (lane & 7) + ((lane >> 3) & 1) * 8;
    const u32 a_base  = base + SM_AH + (u32)((m0 + lr) * 144 + ((lane >> 4) & 1) * 16);
    const u32 al_base = a_base + (SM_AL - SM_AH);
    const u32 b4_off = (u32)((lane & 7) * 144 + ((lane >> 3) & 1) * 16
                             + ((lane >> 4) & 1) * 1152);

    // ---- 32 chunks of 32 codes: approx pass, per-chunk minima only ----
    #pragma unroll 1
    for (int n = 0; n < NCH; n++) {
        CP_WAIT0();
        __syncthreads();                 // B(n) visible; buf (n+1)&1 free

        if (n + 1 < NCH) {
            stage_chunk(base, n + 1, (n + 1) & 1, tid);
            CP_COMMIT();
        }

        const u32 bbh = base + SM_BB + (u32)((n & 1) * 9216);
        const u32 bbl = bbh + 4608;
        float c[4][4];
        #pragma unroll
        for (int nt = 0; nt < 4; nt++)
            #pragma unroll
            for (int q = 0; q < 4; q++) c[nt][q] = 0.0f;

        #pragma unroll
        for (int ks = 0; ks < 4; ks++) {
            u32 ah[4], al4[4], bh0[4], bh1[4], bl0[4], bl1[4];
            LDSM_X4(ah, a_base + ks * 32);
            LDSM_X4(al4, al_base + ks * 32);
            LDSM_X4(bh0, bbh + (u32)(ks * 32) + b4_off);         // rows 0-15
            LDSM_X4(bh1, bbh + (u32)(2304 + ks * 32) + b4_off);  // rows 16-31
            LDSM_X4(bl0, bbl + (u32)(ks * 32) + b4_off);
            LDSM_X4(bl1, bbl + (u32)(2304 + ks * 32) + b4_off);
            MMA_BF16(c[0], ah,  bh0[0], bh0[1]);
            MMA_BF16(c[0], ah,  bl0[0], bl0[1]);
            MMA_BF16(c[0], al4, bh0[0], bh0[1]);
            MMA_BF16(c[1], ah,  bh0[2], bh0[3]);
            MMA_BF16(c[1], ah,  bl0[2], bl0[3]);
            MMA_BF16(c[1], al4, bh0[2], bh0[3]);
            MMA_BF16(c[2], ah,  bh1[0], bh1[1]);
            MMA_BF16(c[2], ah,  bl1[0], bl1[1]);
            MMA_BF16(c[2], al4, bh1[0], bh1[1]);
            MMA_BF16(c[3], ah,  bh1[2], bh1[3]);
            MMA_BF16(c[3], ah,  bl1[2], bl1[3]);
            MMA_BF16(c[3], al4, bh1[2], bh1[3]);
        }

        // fold: s = fma(-2, M~, eB); tree-min per row; quad merge; store MC
        float rm0 = CUDART_INF_F, rm1 = CUDART_INF_F;
        #pragma unroll
        for (int nt = 0; nt < 4; nt++) {
            int col = n * 32 + nt * 8 + 2 * tq;
            float2 eb2 = *(const float2*)&eBs[col];
            float s0 = __fmaf_rn(-2.0f, c[nt][0], eb2.x);
            float s1 = __fmaf_rn(-2.0f, c[nt][1], eb2.y);
            float s2 = __fmaf_rn(-2.0f, c[nt][2], eb2.x);
            float s3 = __fmaf_rn(-2.0f, c[nt][3], eb2.y);
            rm0 = fminf(rm0, fminf(s0, s1));
            rm1 = fminf(rm1, fminf(s2, s3));
        }
        rm0 = fminf(rm0, __shfl_xor_sync(0xffffffffu, rm0, 1));
        rm0 = fminf(rm0, __shfl_xor_sync(0xffffffffu, rm0, 2));
        rm1 = fminf(rm1, __shfl_xor_sync(0xffffffffu, rm1, 1));
        rm1 = fminf(rm1, __shfl_xor_sync(0xffffffffu, rm1, 2));
        if (tq == 0) {
            MC[n * 128 + m0 + g] = rm0;
            MC[n * 128 + m0 + 8 + g] = rm1;
        }
    }
    __syncthreads();

    // ---- certificate: select chunks within EPS of gmin; group by chunk ----
    if (tid < 128) {
        float gmin = CUDART_INF_F;
        #pragma unroll
        for (int c = 0; c < NCH; c++) gmin = fminf(gmin, MC[c * 128 + tid]);
        float thr = __fadd_rn(gmin, EPS);
        for (int c = 0; c < NCH; c++) {
            if (MC[c * 128 + tid] <= thr) {
                int o = atomicAdd(&cntc[c], 1);
                if (o < 32) {
                    plist[c * 32 + o] = (unsigned char)tid;
                } else {
                    // overflow (essentially never): inline exact scan
                    float Ap = As[tid];
                    ull bk = ~0ull;
                    for (int k = c * 32; k < c * 32 + 32; k++) {
                        const float* er = emb + (size_t)k * 64;
                        float M = 0.0f;
                        #pragma unroll 4
                        for (int j = 0; j < 16; j++) {
                            float4 e4 = *(const float4*)(er + j * 4);
                            M = __fmaf_rn(Xs[(j * 4 + 0) * 128 + tid], e4.x, M);
                            M = __fmaf_rn(Xs[(j * 4 + 1) * 128 + tid], e4.y, M);
                            M = __fmaf_rn(Xs[(j * 4 + 2) * 128 + tid], e4.z, M);
                            M = __fmaf_rn(Xs[(j * 4 + 3) * 128 + tid], e4.w, M);
                        }
                        float dk = __fadd_rn(__fmaf_rn(-2.0f, M, Ap), eBs[k]);
                        ull key = ((ull)__float_as_uint(dk) << 32) | (u32)k;
                        bk = bk < key ? bk : key;
                    }
                    atomicMin(&pbest[tid], bk);
                }
            }
        }
    }
    __syncthreads();

    // ---- grouped exact scans: warp = chunk; lanes = positions ----
    for (int c = wid; c < NCH; c += 8) {
        int cnt = cntc[c];
        if (cnt == 0) continue;
        if (cnt > 32) cnt = 32;
        int pos = plist[c * 32 + (lane < cnt ? lane : 0)];
        bool act = lane < cnt;
        float Ap = As[pos];
        ull bk = ~0ull;
        #pragma unroll 1
        for (int k2 = 0; k2 < 32; k2 += 2) {
            int ka = c * 32 + k2;
            const float4* ra = (const float4*)(emb + (size_t)ka * 64);
            const float4* rb = (const float4*)(emb + (size_t)(ka + 1) * 64);
            float Ma = 0.0f, Mb = 0.0f;
            #pragma unroll
            for (int j = 0; j < 16; j++) {
                float4 ea = ra[j];            // broadcast (same addr all lanes)
                float4 eb = rb[j];
                float x0 = Xs[(j * 4 + 0) * 128 + pos];
                float x1 = Xs[(j * 4 + 1) * 128 + pos];
                float x2 = Xs[(j * 4 + 2) * 128 + pos];
                float x3 = Xs[(j * 4 + 3) * 128 + pos];
                Ma = __fmaf_rn(x0, ea.x, Ma); Mb = __fmaf_rn(x0, eb.x, Mb);
                Ma = __fmaf_rn(x1, ea.y, Ma); Mb = __fmaf_rn(x1, eb.y, Mb);
                Ma = __fmaf_rn(x2, ea.z, Ma); Mb = __fmaf_rn(x2, eb.z, Mb);
                Ma = __fmaf_rn(x3, ea.w, Ma); Mb = __fmaf_rn(x3, eb.w, Mb);
            }
            float da = __fadd_rn(__fmaf_rn(-2.0f, Ma, Ap), eBs[ka]);
            float db = __fadd_rn(__fmaf_rn(-2.0f, Mb, Ap), eBs[ka + 1]);
            // d > 0 -> bits order-isomorphic; ascending k in low bits:
            // u64 min == (value, index) lexicographic min, tie -> lowest k
            ull keya = ((ull)__float_as_uint(da) << 32) | (u32)ka;
            ull keyb = ((ull)__float_as_uint(db) << 32) | (u32)(ka + 1);
            bk = bk < keya ? bk : keya;
            bk = bk < keyb ? bk : keyb;
        }
        if (act) atomicMin(&pbest[pos], bk);
    }
    __syncthreads();

    if (tid < 128) {
        int idx = (int)(u32)pbest[tid];
        idxs[tid] = idx;
        if (out_size >= TOTAL_OUT)
            out[ENC_OFF + b * 1024 + p0 + tid] = (float)idx;
    }
    __syncthreads();

    // ---- straight-through output + loss partial ----
    float lsum = 0.0f;
    #pragma unroll
    for (int j = 0; j < 32; j++) {
        int i  = tid + j * 256;
        int pp = i & 127;
        int d  = i >> 7;
        float q  = emb[(size_t)idxs[pp] * 64 + d];
        float xv = Xs[d * 128 + pp];
        float df = __fadd_rn(q, -xv);
        lsum += df * df;
        out[((size_t)b * 64 + d) * 1024 + p0 + pp] = __fadd_rn(xv, df);
    }
    #pragma unroll
    for (int off = 16; off > 0; off >>= 1)
        lsum += __shfl_down_sync(0xffffffffu, lsum, off);
    if (lane == 0) wsum[wid] = lsum;
    __syncthreads();
    if (tid == 0) {
        float t = 0.0f;
        #pragma unroll
        for (int w = 0; w < 8; w++) t += wsum[w];
        atomicAdd(&g_loss_acc, (double)t);
        __threadfence();
        int old = atomicAdd(&g_fin, 1);
        if (old == NTILES - 1) {
            if (out_size >= TOTAL_OUT) {
                float m = (float)(g_loss_acc * (1.0 / 4194304.0));
                out[LOSS_OFF] = __fadd_rn(m, __fmul_rn(0.25f, m));
                out[NLL_OFF]  = 1.0f;
            }
            g_loss_acc = 0.0;       // self-reset for next replay
            g_fin = 0;
        }
    }
}

extern "C" void kernel_launch(void* const* d_in, const int* in_sizes, int n_in,
                              void* d_out, int out_size) {
    const float* x   = (const float*)d_in[0];
    const float* emb = (const float*)d_in[1];
    if (n_in >= 2 && in_sizes[0] == 1024 * 64) {
        const float* t = x; x = emb; emb = t;
    }
    float* out = (float*)d_out;

    cudaFuncSetAttribute(vq_main, cudaFuncAttributeMaxDynamicSharedMemorySize,
                         SM_TOTAL);

    vq_prep<<<256, 256>>>(emb);
    vq_main<<<NTILES, 256, SM_TOTAL>>>(x, emb, out, out_size);
}

// round 15
// speedup vs baseline: 1.4902x; 1.1790x over previous
#include <cuda_runtime.h>
#include <cuda_bf16.h>
#include <math_constants.h>
#include <cstdint>

// VQ-VAE quantizer: SINGLE plain-bf16 mma.sync approx pass -> per-chunk
// minima -> chunk certificate -> grouped EXACT frozen-chain scan.
// Frozen reference pipeline (bitwise): d_k = fl(fl(A-2M_k)+B_k), A = x^2
// float2-leaf tree, M_k = ascending-d fp32 FMA chain, B_k = ascending chain,
// argmin tie -> lowest index.
// Approx: M~ = bf16(x).bf16(e) (f32 acc); s_k = fma(-2, M~, eB_k).
// |s_k - (d_k - A)| <= delta: |2dM| <= 2*2^-8*<|x|,|e|> <= ~3.2e-4 worst
// tail; EPS = 1e-3 >= 3*delta. For k in a chunk outside S = {c: MC[c] <=
// gmin+EPS}: d_k - A >= s_k - delta > gmin + EPS - delta >= s_min + 2delta
// - ... > d_argmin - A strictly => exact argmin (incl. exact ties) in S.
// All winners produced by exact frozen-chain scans => bitwise correct.

#define ENC_OFF   4194304
#define LOSS_OFF  4259840
#define NLL_OFF   4259841
#define TOTAL_OUT 4259842
#define NTILES    512
#define EPS       1.0e-3f
#define BROW      72        // bf16 elems per codebook image row (144 B)
#define NCH       32        // chunks of 32 codes

// smem offsets (bytes)
#define SM_XS    0          // fp32 X tile [64][128]        32768
#define SM_AH    32768      // A bf16 image [128][72]       18432
#define SM_BB    51200      // B bufs x2 (4608 each)         9216
#define SM_MC    60416      // chunk minima [32][128] f32   16384
#define SM_EBS   76800      // fp32 ||e||^2 [1024]           4096
#define SM_AS    80896      // fp32 A [128]                   512
#define SM_IDX   81408      // winners [128]                  512
#define SM_PB    81920      // u64 pbest [128]               1024
#define SM_CNTC  82944      // int cnt per chunk [32]         128
#define SM_PL    83072      // u8 plist [32][32]             1024
#define SM_WSUM  84096      // f32 [8]                         32
#define SM_TOTAL 84224

typedef unsigned long long ull;
typedef unsigned int u32;

__device__ double g_loss_acc;                 // self-reset
__device__ int    g_fin;                      // self-reset
__device__ __align__(16) float g_eB[1024];    // exact ||e||^2 chains
__device__ __align__(16) __nv_bfloat16 g_Bh[1024 * BROW];  // bf16 codebook image

__device__ __forceinline__ void cp16(u32 dst, const void* src) {
    asm volatile("cp.async.cg.shared.global [%0], [%1], 16;"
                 :: "r"(dst), "l"(src) : "memory");
}
#define CP_COMMIT() asm volatile("cp.async.commit_group;" ::: "memory")
#define CP_WAIT0()  asm volatile("cp.async.wait_group 0;" ::: "memory")
#define CP_WAIT1()  asm volatile("cp.async.wait_group 1;" ::: "memory")

#define LDSM_X4(r, a)                                                        \
    asm volatile("ldmatrix.sync.aligned.m8n8.x4.shared.b16 {%0,%1,%2,%3}, [%4];" \
        : "=r"((r)[0]), "=r"((r)[1]), "=r"((r)[2]), "=r"((r)[3]) : "r"(a))
#define MMA_BF16(c, a, b0, b1)                                               \
    asm volatile("mma.sync.aligned.m16n8k16.row.col.f32.bf16.bf16.f32 "      \
        "{%0,%1,%2,%3}, {%4,%5,%6,%7}, {%8,%9}, {%0,%1,%2,%3};"              \
        : "+f"((c)[0]), "+f"((c)[1]), "+f"((c)[2]), "+f"((c)[3])             \
        : "r"((a)[0]), "r"((a)[1]), "r"((a)[2]), "r"((a)[3]), "r"(b0), "r"(b1))

// Kernel 0: bf16 codebook image (padded rows) + exact ||e||^2 chains.
__global__ void __launch_bounds__(256) vq_prep(const float* __restrict__ emb) {
    int t = blockIdx.x * blockDim.x + threadIdx.x;   // 65536
    int k = t >> 6, d = t & 63;
    g_Bh[k * BROW + d] = __float2bfloat16(emb[t]);
    if (t < 1024) {
        const float* row = emb + (size_t)t * 64;
        float b = 0.0f;
        #pragma unroll
        for (int i = 0; i < 64; i++) b = __fmaf_rn(row[i], row[i], b);
        g_eB[t] = b;
    }
}

// stage one 32-code chunk (4608 B) into buffer `buf`
__device__ __forceinline__ void stage_chunk(u32 base, int c, int buf, int tid) {
    u32 dst = base + SM_BB + (u32)(buf * 4608);
    const char* sh = (const char*)g_Bh + c * 4608;
    cp16(dst + tid * 16, sh + tid * 16);                      // 256 chunks
    if (tid < 32)
        cp16(dst + (256 + tid) * 16, sh + (256 + tid) * 16);  // remaining 32
}

__global__ void __launch_bounds__(256, 2)
vq_main(const float* __restrict__ x, const float* __restrict__ emb,
        float* __restrict__ out, int out_size) {
    extern __shared__ __align__(1024) unsigned char sm[];
    float* Xs    = (float*)(sm + SM_XS);
    float* MC    = (float*)(sm + SM_MC);
    float* eBs   = (float*)(sm + SM_EBS);
    float* As    = (float*)(sm + SM_AS);
    int*   idxs  = (int*)(sm + SM_IDX);
    ull*   pbest = (ull*)(sm + SM_PB);
    int*   cntc  = (int*)(sm + SM_CNTC);
    unsigned char* plist = (unsigned char*)(sm + SM_PL);
    float* wsum  = (float*)(sm + SM_WSUM);

    const u32 base = (u32)__cvta_generic_to_shared(sm);
    const int tid = threadIdx.x;
    const int wid = tid >> 5, lane = tid & 31;
    const int b  = blockIdx.x >> 3;
    const int p0 = (blockIdx.x & 7) * 128;
    const int m0 = wid * 16;

    // ---- prologue: group0 = X + eB, group1 = B chunk 0; init aux ----
    {
        const float* xb = x + (size_t)b * 65536 + p0;
        #pragma unroll
        for (int i = 0; i < 8; i++) {
            int c = tid + i * 256;           // 2048 16B-chunks
            int d = c >> 5, po = c & 31;
            cp16(base + SM_XS + d * 512 + po * 16, xb + d * 1024 + po * 4);
        }
        cp16(base + SM_EBS + tid * 16, (const char*)g_eB + tid * 16);
        CP_COMMIT();
        stage_chunk(base, 0, 0, tid);
        CP_COMMIT();
        if (tid < 128) pbest[tid] = ~0ull;
        if (tid < NCH) cntc[tid] = 0;
        CP_WAIT1();     // X + eB landed
    }
    __syncthreads();

    // ---- build A bf16 image + exact A (frozen tree) ----
    if (tid < 128) {
        #pragma unroll
        for (int d2 = 0; d2 < 32; d2++) {
            float v0 = Xs[(2 * d2) * 128 + tid];
            float v1 = Xs[(2 * d2 + 1) * 128 + tid];
            __nv_bfloat16 h0 = __float2bfloat16(v0), h1 = __float2bfloat16(v1);
            u32 hw = (u32)*(unsigned short*)&h0 | ((u32)*(unsigned short*)&h1 << 16);
            *(u32*)(sm + SM_AH + tid * 144 + d2 * 4) = hw;
        }
        float l[32];
        #pragma unroll
        for (int t = 0; t < 32; t++) {
            float a = Xs[(2 * t) * 128 + tid];
            float c = Xs[(2 * t + 1) * 128 + tid];
            l[t] = __fmaf_rn(c, c, __fmul_rn(a, a));
        }
        #pragma unroll
        for (int off = 16; off >= 1; off >>= 1)
            #pragma unroll
            for (int t = 0; t < 16; t++)
                if (t < off) l[t] = __fadd_rn(l[t], l[t + off]);
        As[tid] = l[0];
    }
    __syncthreads();

    // per-lane fragment addressing (validated R12-R14: rel_err 0)
    const int g = lane >> 2, tq = lane & 3;
    const int lr = (lane & 7) + ((lane >> 3) & 1) * 8;
    const u32 a_base = base + SM_AH + (u32)((m0 + lr) * 144 + ((lane >> 4) & 1) * 16);
    const u32 b4_off = (u32)((lane & 7) * 144 + ((lane >> 3) & 1) * 16
                             + ((lane >> 4) & 1) * 1152);

    // hoist A fragments (chunk-invariant): 16 regs
    u32 ahf[4][4];
    #pragma unroll
    for (int ks = 0; ks < 4; ks++) LDSM_X4(ahf[ks], a_base + ks * 32);

    // ---- 32 chunks of 32 codes: approx pass, per-chunk minima only ----
    #pragma unroll 1
    for (int n = 0; n < NCH; n++) {
        CP_WAIT0();
        __syncthreads();                 // B(n) visible; buf (n+1)&1 free

        if (n + 1 < NCH) {
            stage_chunk(base, n + 1, (n + 1) & 1, tid);
            CP_COMMIT();
        }

        const u32 bbh = base + SM_BB + (u32)((n & 1) * 4608);
        float c4[4][4];
        #pragma unroll
        for (int nt = 0; nt < 4; nt++)
            #pragma unroll
            for (int q = 0; q < 4; q++) c4[nt][q] = 0.0f;

        #pragma unroll
        for (int ks = 0; ks < 4; ks++) {
            u32 bh0[4], bh1[4];
            LDSM_X4(bh0, bbh + (u32)(ks * 32) + b4_off);         // rows 0-15
            LDSM_X4(bh1, bbh + (u32)(2304 + ks * 32) + b4_off);  // rows 16-31
            MMA_BF16(c4[0], ahf[ks], bh0[0], bh0[1]);
            MMA_BF16(c4[1], ahf[ks], bh0[2], bh0[3]);
            MMA_BF16(c4[2], ahf[ks], bh1[0], bh1[1]);
            MMA_BF16(c4[3], ahf[ks], bh1[2], bh1[3]);
        }

        // fold: s = fma(-2, M~, eB); tree-min; quad merge; store MC
        float rm0 = CUDART_INF_F, rm1 = CUDART_INF_F;
        #pragma unroll
        for (int nt = 0; nt < 4; nt++) {
            int col = n * 32 + nt * 8 + 2 * tq;
            float2 eb2 = *(const float2*)&eBs[col];
            float s0 = __fmaf_rn(-2.0f, c4[nt][0], eb2.x);
            float s1 = __fmaf_rn(-2.0f, c4[nt][1], eb2.y);
            float s2 = __fmaf_rn(-2.0f, c4[nt][2], eb2.x);
            float s3 = __fmaf_rn(-2.0f, c4[nt][3], eb2.y);
            rm0 = fminf(rm0, fminf(s0, s1));
            rm1 = fminf(rm1, fminf(s2, s3));
        }
        rm0 = fminf(rm0, __shfl_xor_sync(0xffffffffu, rm0, 1));
        rm0 = fminf(rm0, __shfl_xor_sync(0xffffffffu, rm0, 2));
        rm1 = fminf(rm1, __shfl_xor_sync(0xffffffffu, rm1, 1));
        rm1 = fminf(rm1, __shfl_xor_sync(0xffffffffu, rm1, 2));
        if (tq == 0) {
            MC[n * 128 + m0 + g] = rm0;
            MC[n * 128 + m0 + 8 + g] = rm1;
        }
    }
    __syncthreads();

    // ---- certificate: chunks within EPS of gmin; group by chunk ----
    if (tid < 128) {
        float gmin = CUDART_INF_F;
        #pragma unroll
        for (int c = 0; c < NCH; c++) gmin = fminf(gmin, MC[c * 128 + tid]);
        float thr = __fadd_rn(gmin, EPS);
        for (int c = 0; c < NCH; c++) {
            if (MC[c * 128 + tid] <= thr) {
                int o = atomicAdd(&cntc[c], 1);
                if (o < 32) {
                    plist[c * 32 + o] = (unsigned char)tid;
                } else {
                    // overflow (essentially never): inline exact scan
                    float Ap = As[tid];
                    ull bk = ~0ull;
                    for (int k = c * 32; k < c * 32 + 32; k++) {
                        const float* er = emb + (size_t)k * 64;
                        float M = 0.0f;
                        #pragma unroll 4
                        for (int j = 0; j < 16; j++) {
                            float4 e4 = *(const float4*)(er + j * 4);
                            M = __fmaf_rn(Xs[(j * 4 + 0) * 128 + tid], e4.x, M);
                            M = __fmaf_rn(Xs[(j * 4 + 1) * 128 + tid], e4.y, M);
                            M = __fmaf_rn(Xs[(j * 4 + 2) * 128 + tid], e4.z, M);
                            M = __fmaf_rn(Xs[(j * 4 + 3) * 128 + tid], e4.w, M);
                        }
                        float dk = __fadd_rn(__fmaf_rn(-2.0f, M, Ap), eBs[k]);
                        ull key = ((ull)__float_as_uint(dk) << 32) | (u32)k;
                        bk = bk < key ? bk : key;
                    }
                    atomicMin(&pbest[tid], bk);
                }
            }
        }
    }
    __syncthreads();

    // ---- grouped exact scans: warp = chunk; lanes = positions.
    //      Register-blocked: M[32] accumulators, x staged 16 dims/pass;
    //      ascending-d chain across passes == frozen order, bitwise. ----
    for (int c = wid; c < NCH; c += 8) {
        int cnt = cntc[c];
        if (cnt == 0) continue;
        if (cnt > 32) cnt = 32;
        int pos = plist[c * 32 + (lane < cnt ? lane : 0)];
        bool act = lane < cnt;
        float Ap = As[pos];
        float M[32];
        #pragma unroll
        for (int k = 0; k < 32; k++) M[k] = 0.0f;
        #pragma unroll 1
        for (int dd = 0; dd < 4; dd++) {
            float xv[16];
            #pragma unroll
            for (int j = 0; j < 16; j++) xv[j] = Xs[(dd * 16 + j) * 128 + pos];
            #pragma unroll
            for (int k = 0; k < 32; k++) {
                const float4* er = (const float4*)(emb + (size_t)(c * 32 + k) * 64 + dd * 16);
                float4 e0 = er[0], e1 = er[1], e2 = er[2], e3 = er[3];
                float m = M[k];
                m = __fmaf_rn(xv[0],  e0.x, m); m = __fmaf_rn(xv[1],  e0.y, m);
                m = __fmaf_rn(xv[2],  e0.z, m); m = __fmaf_rn(xv[3],  e0.w, m);
                m = __fmaf_rn(xv[4],  e1.x, m); m = __fmaf_rn(xv[5],  e1.y, m);
                m = __fmaf_rn(xv[6],  e1.z, m); m = __fmaf_rn(xv[7],  e1.w, m);
                m = __fmaf_rn(xv[8],  e2.x, m); m = __fmaf_rn(xv[9],  e2.y, m);
                m = __fmaf_rn(xv[10], e2.z, m); m = __fmaf_rn(xv[11], e2.w, m);
                m = __fmaf_rn(xv[12], e3.x, m); m = __fmaf_rn(xv[13], e3.y, m);
                m = __fmaf_rn(xv[14], e3.z, m); m = __fmaf_rn(xv[15], e3.w, m);
                M[k] = m;
            }
        }
        ull bk = ~0ull;
        #pragma unroll
        for (int k = 0; k < 32; k++) {
            int kk = c * 32 + k;
            float dk = __fadd_rn(__fmaf_rn(-2.0f, M[k], Ap), eBs[kk]);
            // d > 0 -> bits order-isomorphic; ascending k in low bits:
            // u64 min == lexicographic (value, index) min, tie -> lowest k
            ull key = ((ull)__float_as_uint(dk) << 32) | (u32)kk;
            bk = bk < key ? bk : key;
        }
        if (act) atomicMin(&pbest[pos], bk);
    }
    __syncthreads();

    if (tid < 128) {
        int idx = (int)(u32)pbest[tid];
        idxs[tid] = idx;
        if (out_size >= TOTAL_OUT)
            out[ENC_OFF + b * 1024 + p0 + tid] = (float)idx;
    }
    __syncthreads();

    // ---- straight-through output + loss partial ----
    float lsum = 0.0f;
    #pragma unroll
    for (int j = 0; j < 32; j++) {
        int i  = tid + j * 256;
        int pp = i & 127;
        int d  = i >> 7;
        float q  = emb[(size_t)idxs[pp] * 64 + d];
        float xv = Xs[d * 128 + pp];
        float df = __fadd_rn(q, -xv);
        lsum += df * df;
        out[((size_t)b * 64 + d) * 1024 + p0 + pp] = __fadd_rn(xv, df);
    }
    #pragma unroll
    for (int off = 16; off > 0; off >>= 1)
        lsum += __shfl_down_sync(0xffffffffu, lsum, off);
    if (lane == 0) wsum[wid] = lsum;
    __syncthreads();
    if (tid == 0) {
        float t = 0.0f;
        #pragma unroll
        for (int w = 0; w < 8; w++) t += wsum[w];
        atomicAdd(&g_loss_acc, (double)t);
        __threadfence();
        int old = atomicAdd(&g_fin, 1);
        if (old == NTILES - 1) {
            if (out_size >= TOTAL_OUT) {
                float m = (float)(g_loss_acc * (1.0 / 4194304.0));
                out[LOSS_OFF] = __fadd_rn(m, __fmul_rn(0.25f, m));
                out[NLL_OFF]  = 1.0f;
            }
            g_loss_acc = 0.0;       // self-reset for next replay
            g_fin = 0;
        }
    }
}

extern "C" void kernel_launch(void* const* d_in, const int* in_sizes, int n_in,
                              void* d_out, int out_size) {
    const float* x   = (const float*)d_in[0];
    const float* emb = (const float*)d_in[1];
    if (n_in >= 2 && in_sizes[0] == 1024 * 64) {
        const float* t = x; x = emb; emb = t;
    }
    float* out = (float*)d_out;

    cudaFuncSetAttribute(vq_main, cudaFuncAttributeMaxDynamicSharedMemorySize,
                         SM_TOTAL);

    vq_prep<<<256, 256>>>(emb);
    vq_main<<<NTILES, 256, SM_TOTAL>>>(x, emb, out, out_size);
}